// round 5
// baseline (speedup 1.0000x reference)
#include <cuda_runtime.h>
#include <cuda_bf16.h>
#include <math.h>
#include <stdint.h>

// Problem constants
#define BB 64
#define TT 1024
#define DD 128
#define HH 256

// Scratch ping-pong buffers [B*T*H] fp32 (64 MB each)
__device__ float g_bufA[(size_t)BB * TT * HH];
__device__ float g_bufB[(size_t)BB * TT * HH];

// ---------------------------------------------------------------------------
// helpers
// ---------------------------------------------------------------------------
__device__ __forceinline__ uint32_t smem_u32(const void* p) {
    uint32_t a;
    asm("{ .reg .u64 t; cvta.to.shared.u64 t, %1; cvt.u32.u64 %0, t; }"
        : "=r"(a) : "l"(p));
    return a;
}

__device__ __forceinline__ void mbar_init(uint32_t addr, uint32_t count) {
    asm volatile("mbarrier.init.shared.b64 [%0], %1;" :: "r"(addr), "r"(count) : "memory");
}

__device__ __forceinline__ void mbar_wait_parity_acq_cluster(uint32_t addr, uint32_t parity) {
    asm volatile(
        "{\n\t"
        ".reg .pred P;\n\t"
        "WAIT_LOOP_%=:\n\t"
        "mbarrier.try_wait.parity.acquire.cluster.shared::cta.b64 P, [%0], %1, 0x989680;\n\t"
        "@!P bra WAIT_LOOP_%=;\n\t"
        "}"
        :: "r"(addr), "r"(parity) : "memory");
}

// ---------------------------------------------------------------------------
// GEMM: C[M,N] = A[M,K] @ W[N,K]^T + b1[n] + b2[n]
// BM=128, BN=128, BK=16, 256 threads, TM=8, TN=8, packed f32x2 accumulators.
// ---------------------------------------------------------------------------
__global__ __launch_bounds__(256)
void gemm_bias_kernel(const float* __restrict__ A,
                      const float* __restrict__ W,
                      const float* __restrict__ b1,
                      const float* __restrict__ b2,
                      float* __restrict__ C,
                      int M, int N, int K)
{
    __shared__ float As[16][128];
    __shared__ float Ws[16][128];

    const int m0 = blockIdx.y * 128;
    const int n0 = blockIdx.x * 128;
    const int tid = threadIdx.x;
    const int tr = tid >> 4;
    const int tc = tid & 15;

    uint64_t acc2[8][4];
#pragma unroll
    for (int i = 0; i < 8; i++)
#pragma unroll
        for (int l = 0; l < 4; l++) acc2[i][l] = 0ull;

    for (int k0 = 0; k0 < K; k0 += 16) {
#pragma unroll
        for (int it = 0; it < 2; it++) {
            int id  = tid + it * 256;
            int row = id >> 2;
            int c4  = (id & 3) << 2;
            float4 v = *(const float4*)&A[(size_t)(m0 + row) * K + k0 + c4];
            As[c4 + 0][row] = v.x;
            As[c4 + 1][row] = v.y;
            As[c4 + 2][row] = v.z;
            As[c4 + 3][row] = v.w;
        }
#pragma unroll
        for (int it = 0; it < 2; it++) {
            int id  = tid + it * 256;
            int row = id >> 2;
            int c4  = (id & 3) << 2;
            float4 v = *(const float4*)&W[(size_t)(n0 + row) * K + k0 + c4];
            Ws[c4 + 0][row] = v.x;
            Ws[c4 + 1][row] = v.y;
            Ws[c4 + 2][row] = v.z;
            Ws[c4 + 3][row] = v.w;
        }
        __syncthreads();

#pragma unroll
        for (int k = 0; k < 16; k++) {
            float a[8];
#pragma unroll
            for (int i = 0; i < 8; i++) a[i] = As[k][tr * 8 + i];
            uint64_t w2[4];
            const uint64_t* wp = (const uint64_t*)&Ws[k][tc * 8];
#pragma unroll
            for (int l = 0; l < 4; l++) w2[l] = wp[l];
#pragma unroll
            for (int i = 0; i < 8; i++) {
                uint64_t a2;
                asm("mov.b64 %0, {%1, %1};" : "=l"(a2) : "f"(a[i]));
#pragma unroll
                for (int l = 0; l < 4; l++)
                    asm("fma.rn.f32x2 %0, %1, %2, %0;"
                        : "+l"(acc2[i][l]) : "l"(a2), "l"(w2[l]));
            }
        }
        __syncthreads();
    }

    float bb[8];
#pragma unroll
    for (int l = 0; l < 8; l++) {
        int n = n0 + tc * 8 + l;
        bb[l] = b1[n] + b2[n];
    }
#pragma unroll
    for (int i = 0; i < 8; i++) {
        float r[8];
#pragma unroll
        for (int l = 0; l < 4; l++) {
            uint32_t lo, hi;
            asm("mov.b64 {%0, %1}, %2;" : "=r"(lo), "=r"(hi) : "l"(acc2[i][l]));
            r[2 * l]     = __uint_as_float(lo) + bb[2 * l];
            r[2 * l + 1] = __uint_as_float(hi) + bb[2 * l + 1];
        }
        float* crow = &C[(size_t)(m0 + tr * 8 + i) * N + n0 + tc * 8];
        *(float4*)crow       = make_float4(r[0], r[1], r[2], r[3]);
        *(float4*)(crow + 4) = make_float4(r[4], r[5], r[6], r[7]);
    }
}

// ---------------------------------------------------------------------------
// Recurrence, 2-CTA cluster per batch element; warp-pair k-split.
//   Lane pair (2i, 2i+1) of warp w owns output j = rank*128 + w*16 + i.
//   kh = lane&1 selects k-half [kh*128, +128); 64 packed f32x2 weights in RF.
//   Per step: mbar wait (remote h) -> FMA -> shfl.bfly reduce -> tanh ->
//   even lane: local hb store; ONE __syncthreads (certifies reads done +
//   local publish); odd lane: remote st + arrive (count=128); even lane: STG.
// ---------------------------------------------------------------------------
template <bool TRANS>
__global__ __launch_bounds__(256, 1) __cluster_dims__(2, 1, 1)
void rec_cluster_kernel(const float* __restrict__ xw,    // [B, T, H]
                        const float* __restrict__ Whh,   // [H, H]
                        float* __restrict__ out)
{
    __shared__ __align__(16) float hb[2][HH];
    __shared__ uint64_t mbar;

    const int t0   = threadIdx.x;
    const int wid  = t0 >> 5;
    const int lane = t0 & 31;
    const int kh   = lane & 1;
    const int jp   = (wid << 4) + (lane >> 1);   // 0..127
    uint32_t rank;
    asm("mov.u32 %0, %%cluster_ctarank;" : "=r"(rank));
    const int b = blockIdx.x >> 1;
    const int j = (int)rank * 128 + jp;

    // 128 fp32 weights = 64 packed f32x2 pairs, all in registers.
    uint64_t w[64];
    const uint64_t* wrow = (const uint64_t*)(Whh + (size_t)j * HH + (kh << 7));
#pragma unroll
    for (int i = 0; i < 64; i++) w[i] = wrow[i];

    hb[0][t0] = 0.0f;
    hb[1][t0] = 0.0f;
    const uint32_t mb = smem_u32(&mbar);
    if (t0 == 0) mbar_init(mb, 128);   // 128 remote arrivals per step (odd lanes of peer)
    __syncthreads();
    asm volatile("barrier.cluster.arrive.aligned;" ::: "memory");
    asm volatile("barrier.cluster.wait.aligned;"   ::: "memory");

    const uint32_t peer = rank ^ 1u;
    uint32_t r_h0, r_h1, r_mb;
    {
        uint32_t l_h0 = smem_u32(&hb[0][j]);
        uint32_t l_h1 = smem_u32(&hb[1][j]);
        asm("mapa.shared::cluster.u32 %0, %1, %2;" : "=r"(r_h0) : "r"(l_h0), "r"(peer));
        asm("mapa.shared::cluster.u32 %0, %1, %2;" : "=r"(r_h1) : "r"(l_h1), "r"(peer));
        asm("mapa.shared::cluster.u32 %0, %1, %2;" : "=r"(r_mb) : "r"(mb),   "r"(peer));
    }

    const float* xp = xw + (size_t)b * TT * HH + j;
    float xin = xp[0];

    int p = 0;
    for (int t = 0; t < TT; ++t) {
        // Wait for peer's h of step t-1 (acquire). Local h ordered by bar below.
        if (t) mbar_wait_parity_acq_cluster(mb, (uint32_t)((t - 1) & 1));

        float xnext = (t + 1 < TT) ? xp[(size_t)(t + 1) * HH] : 0.0f;

        const uint64_t* h2 = (const uint64_t*)(hb[p] + (kh << 7));
        uint64_t a0 = 0ull, a1 = 0ull, a2 = 0ull, a3 = 0ull;
#pragma unroll
        for (int i = 0; i < 64; i += 4) {
            asm("fma.rn.f32x2 %0, %1, %2, %0;" : "+l"(a0) : "l"(w[i + 0]), "l"(h2[i + 0]));
            asm("fma.rn.f32x2 %0, %1, %2, %0;" : "+l"(a1) : "l"(w[i + 1]), "l"(h2[i + 1]));
            asm("fma.rn.f32x2 %0, %1, %2, %0;" : "+l"(a2) : "l"(w[i + 2]), "l"(h2[i + 2]));
            asm("fma.rn.f32x2 %0, %1, %2, %0;" : "+l"(a3) : "l"(w[i + 3]), "l"(h2[i + 3]));
        }
        asm("add.rn.f32x2 %0, %0, %1;" : "+l"(a0) : "l"(a1));
        asm("add.rn.f32x2 %0, %0, %1;" : "+l"(a2) : "l"(a3));
        asm("add.rn.f32x2 %0, %0, %1;" : "+l"(a0) : "l"(a2));
        uint32_t lo, hi;
        asm("mov.b64 {%0, %1}, %2;" : "=r"(lo), "=r"(hi) : "l"(a0));
        float part = __uint_as_float(lo) + __uint_as_float(hi);

        // Intra-warp pair reduce: both lanes end up with the full dot.
        part += __shfl_xor_sync(0xffffffffu, part, 1);

        float hval;
        {
            float v = xin + part;
            asm("tanh.approx.f32 %0, %1;" : "=f"(hval) : "f"(v));
        }

        // Local publish (even lane), BEFORE the bar so the bar orders it.
        if (!kh) hb[p ^ 1][j] = hval;

        __syncthreads();   // all reads of hb[p] done + local h visible

        if (kh) {
            // Remote publish + arrive (release at cluster scope).
            asm volatile("st.shared::cluster.f32 [%0], %1;"
                         :: "r"(p ? r_h0 : r_h1), "f"(hval) : "memory");
            asm volatile("mbarrier.arrive.release.cluster.shared::cluster.b64 _, [%0];"
                         :: "r"(r_mb) : "memory");
        } else {
            // Out-store off the critical path.
            if (TRANS) out[((size_t)b * HH + j) * TT + t] = hval;
            else       out[((size_t)b * TT + t) * HH + j] = hval;
        }
        xin = xnext;
        p ^= 1;
    }

    asm volatile("barrier.cluster.arrive.aligned;" ::: "memory");
    asm volatile("barrier.cluster.wait.aligned;"   ::: "memory");
}

// ---------------------------------------------------------------------------
// Launch
// ---------------------------------------------------------------------------
extern "C" void kernel_launch(void* const* d_in, const int* in_sizes, int n_in,
                              void* d_out, int out_size)
{
    const float* x     = (const float*)d_in[0];
    const float* W_ih0 = (const float*)d_in[1];
    const float* W_hh0 = (const float*)d_in[2];
    const float* b_ih0 = (const float*)d_in[3];
    const float* b_hh0 = (const float*)d_in[4];
    const float* W_ih1 = (const float*)d_in[5];
    const float* W_hh1 = (const float*)d_in[6];
    const float* b_ih1 = (const float*)d_in[7];
    const float* b_hh1 = (const float*)d_in[8];
    float* out = (float*)d_out;

    float *bufA, *bufB;
    cudaGetSymbolAddress((void**)&bufA, g_bufA);
    cudaGetSymbolAddress((void**)&bufB, g_bufB);

    const int M = BB * TT;  // 65536

    // Layer 1 input projection: bufA = x @ W_ih0^T + (b_ih0 + b_hh0)
    gemm_bias_kernel<<<dim3(HH / 128, M / 128), 256>>>(
        x, W_ih0, b_ih0, b_hh0, bufA, M, HH, DD);

    // Layer 1 recurrence -> bufB = h1 [B,T,H]   (64 clusters of 2 CTAs)
    rec_cluster_kernel<false><<<BB * 2, 256>>>(bufA, W_hh0, bufB);

    // Layer 2 input projection: bufA = h1 @ W_ih1^T + (b_ih1 + b_hh1)
    gemm_bias_kernel<<<dim3(HH / 128, M / 128), 256>>>(
        bufB, W_ih1, b_ih1, b_hh1, bufA, M, HH, HH);

    // Layer 2 recurrence -> out [B,H,T]
    rec_cluster_kernel<true><<<BB * 2, 256>>>(bufA, W_hh1, out);
}

// round 6
// speedup vs baseline: 1.2864x; 1.2864x over previous
#include <cuda_runtime.h>
#include <cuda_bf16.h>
#include <math.h>
#include <stdint.h>

// Problem constants
#define BB 64
#define TT 1024
#define DD 128
#define HH 256

// Scratch ping-pong buffers [B*T*H] fp32 (64 MB each)
__device__ float g_bufA[(size_t)BB * TT * HH];
__device__ float g_bufB[(size_t)BB * TT * HH];

// ---------------------------------------------------------------------------
// helpers
// ---------------------------------------------------------------------------
__device__ __forceinline__ uint32_t smem_u32(const void* p) {
    uint32_t a;
    asm("{ .reg .u64 t; cvta.to.shared.u64 t, %1; cvt.u32.u64 %0, t; }"
        : "=r"(a) : "l"(p));
    return a;
}

__device__ __forceinline__ void mbar_init(uint32_t addr, uint32_t count) {
    asm volatile("mbarrier.init.shared.b64 [%0], %1;" :: "r"(addr), "r"(count) : "memory");
}

__device__ __forceinline__ void mbar_wait_parity_acq_cluster(uint32_t addr, uint32_t parity) {
    asm volatile(
        "{\n\t"
        ".reg .pred P;\n\t"
        "WAIT_LOOP_%=:\n\t"
        "mbarrier.try_wait.parity.acquire.cluster.shared::cta.b64 P, [%0], %1, 0x989680;\n\t"
        "@!P bra WAIT_LOOP_%=;\n\t"
        "}"
        :: "r"(addr), "r"(parity) : "memory");
}

// ---------------------------------------------------------------------------
// GEMM: C[M,N] = A[M,K] @ W[N,K]^T + b1[n] + b2[n]
// BM=128, BN=128, BK=16, 256 threads, TM=8, TN=8, packed f32x2 accumulators.
// ---------------------------------------------------------------------------
__global__ __launch_bounds__(256)
void gemm_bias_kernel(const float* __restrict__ A,
                      const float* __restrict__ W,
                      const float* __restrict__ b1,
                      const float* __restrict__ b2,
                      float* __restrict__ C,
                      int M, int N, int K)
{
    __shared__ float As[16][128];
    __shared__ float Ws[16][128];

    const int m0 = blockIdx.y * 128;
    const int n0 = blockIdx.x * 128;
    const int tid = threadIdx.x;
    const int tr = tid >> 4;
    const int tc = tid & 15;

    uint64_t acc2[8][4];
#pragma unroll
    for (int i = 0; i < 8; i++)
#pragma unroll
        for (int l = 0; l < 4; l++) acc2[i][l] = 0ull;

    for (int k0 = 0; k0 < K; k0 += 16) {
#pragma unroll
        for (int it = 0; it < 2; it++) {
            int id  = tid + it * 256;
            int row = id >> 2;
            int c4  = (id & 3) << 2;
            float4 v = *(const float4*)&A[(size_t)(m0 + row) * K + k0 + c4];
            As[c4 + 0][row] = v.x;
            As[c4 + 1][row] = v.y;
            As[c4 + 2][row] = v.z;
            As[c4 + 3][row] = v.w;
        }
#pragma unroll
        for (int it = 0; it < 2; it++) {
            int id  = tid + it * 256;
            int row = id >> 2;
            int c4  = (id & 3) << 2;
            float4 v = *(const float4*)&W[(size_t)(n0 + row) * K + k0 + c4];
            Ws[c4 + 0][row] = v.x;
            Ws[c4 + 1][row] = v.y;
            Ws[c4 + 2][row] = v.z;
            Ws[c4 + 3][row] = v.w;
        }
        __syncthreads();

#pragma unroll
        for (int k = 0; k < 16; k++) {
            float a[8];
#pragma unroll
            for (int i = 0; i < 8; i++) a[i] = As[k][tr * 8 + i];
            uint64_t w2[4];
            const uint64_t* wp = (const uint64_t*)&Ws[k][tc * 8];
#pragma unroll
            for (int l = 0; l < 4; l++) w2[l] = wp[l];
#pragma unroll
            for (int i = 0; i < 8; i++) {
                uint64_t a2;
                asm("mov.b64 %0, {%1, %1};" : "=l"(a2) : "f"(a[i]));
#pragma unroll
                for (int l = 0; l < 4; l++)
                    asm("fma.rn.f32x2 %0, %1, %2, %0;"
                        : "+l"(acc2[i][l]) : "l"(a2), "l"(w2[l]));
            }
        }
        __syncthreads();
    }

    float bb[8];
#pragma unroll
    for (int l = 0; l < 8; l++) {
        int n = n0 + tc * 8 + l;
        bb[l] = b1[n] + b2[n];
    }
#pragma unroll
    for (int i = 0; i < 8; i++) {
        float r[8];
#pragma unroll
        for (int l = 0; l < 4; l++) {
            uint32_t lo, hi;
            asm("mov.b64 {%0, %1}, %2;" : "=r"(lo), "=r"(hi) : "l"(acc2[i][l]));
            r[2 * l]     = __uint_as_float(lo) + bb[2 * l];
            r[2 * l + 1] = __uint_as_float(hi) + bb[2 * l + 1];
        }
        float* crow = &C[(size_t)(m0 + tr * 8 + i) * N + n0 + tc * 8];
        *(float4*)crow       = make_float4(r[0], r[1], r[2], r[3]);
        *(float4*)(crow + 4) = make_float4(r[4], r[5], r[6], r[7]);
    }
}

// ---------------------------------------------------------------------------
// Recurrence, 2-CTA cluster per batch element.
//   CTA rank r owns outputs j in [r*128, +128). Thread (jl = t0&127, kh = t0>>7)
//   computes the kh-half partial dot for output j = r*128 + jl.
//   kh == r   : "helper"  — reads locally-produced h, never waits the mbar.
//               Computes during the DSMEM hop, posts red[jl], bar.arrive 1.
//   kh != r   : "waiter"  — waits peer h (mbar), computes peer-half, joins the
//               helper partial via bar.sync 1, applies tanh, publishes
//               remote (st.cluster + mbar arrive FIRST), then local hb,
//               out STG, bar.arrive 2. Helpers gate their next read on
//               bar.sync 2.
//   Named barriers: id1 = red handoff, id2 = local h publish. 256 arrivals each.
// ---------------------------------------------------------------------------
template <bool TRANS>
__global__ __launch_bounds__(256, 1) __cluster_dims__(2, 1, 1)
void rec_cluster_kernel(const float* __restrict__ xw,    // [B, T, H]
                        const float* __restrict__ Whh,   // [H, H]
                        float* __restrict__ out)
{
    __shared__ __align__(16) float hb[2][HH];
    __shared__ float red[128];
    __shared__ uint64_t mbar;

    const int t0 = threadIdx.x;
    const int jl = t0 & 127;
    const int kh = t0 >> 7;
    uint32_t rank;
    asm("mov.u32 %0, %%cluster_ctarank;" : "=r"(rank));
    const int b = blockIdx.x >> 1;
    const int j = (int)rank * 128 + jl;
    const bool waiter = (kh != (int)rank);

    // 128 fp32 weights = 64 packed f32x2 pairs, all in registers.
    uint64_t w[64];
    const uint64_t* wrow = (const uint64_t*)(Whh + (size_t)j * HH + (kh << 7));
#pragma unroll
    for (int i = 0; i < 64; i++) w[i] = wrow[i];

    hb[0][t0] = 0.0f;
    hb[1][t0] = 0.0f;
    const uint32_t mb = smem_u32(&mbar);
    if (t0 == 0) mbar_init(mb, 128);   // 128 remote arrivals (peer's waiters) per step
    __syncthreads();
    asm volatile("barrier.cluster.arrive.aligned;" ::: "memory");
    asm volatile("barrier.cluster.wait.aligned;"   ::: "memory");

    const uint32_t peer = rank ^ 1u;
    uint32_t r_h0, r_h1, r_mb;
    {
        uint32_t l_h0 = smem_u32(&hb[0][j]);
        uint32_t l_h1 = smem_u32(&hb[1][j]);
        asm("mapa.shared::cluster.u32 %0, %1, %2;" : "=r"(r_h0) : "r"(l_h0), "r"(peer));
        asm("mapa.shared::cluster.u32 %0, %1, %2;" : "=r"(r_h1) : "r"(l_h1), "r"(peer));
        asm("mapa.shared::cluster.u32 %0, %1, %2;" : "=r"(r_mb) : "r"(mb),   "r"(peer));
    }

    const float* xp = xw + (size_t)b * TT * HH + j;
    float xin = waiter ? xp[0] : 0.0f;

    int p = 0;
    if (waiter) {
        for (int t = 0; t < TT; ++t) {
            if (t) mbar_wait_parity_acq_cluster(mb, (uint32_t)((t - 1) & 1));

            float xnext = (t + 1 < TT) ? xp[(size_t)(t + 1) * HH] : 0.0f;

            const ulonglong2* h4 = (const ulonglong2*)(hb[p] + (kh << 7));
            uint64_t a0 = 0ull, a1 = 0ull, a2 = 0ull, a3 = 0ull;
#pragma unroll
            for (int i = 0; i < 32; i += 2) {
                ulonglong2 hv0 = h4[i];
                ulonglong2 hv1 = h4[i + 1];
                asm("fma.rn.f32x2 %0, %1, %2, %0;" : "+l"(a0) : "l"(w[2*i + 0]), "l"(hv0.x));
                asm("fma.rn.f32x2 %0, %1, %2, %0;" : "+l"(a1) : "l"(w[2*i + 1]), "l"(hv0.y));
                asm("fma.rn.f32x2 %0, %1, %2, %0;" : "+l"(a2) : "l"(w[2*i + 2]), "l"(hv1.x));
                asm("fma.rn.f32x2 %0, %1, %2, %0;" : "+l"(a3) : "l"(w[2*i + 3]), "l"(hv1.y));
            }
            asm("add.rn.f32x2 %0, %0, %1;" : "+l"(a0) : "l"(a1));
            asm("add.rn.f32x2 %0, %0, %1;" : "+l"(a2) : "l"(a3));
            asm("add.rn.f32x2 %0, %0, %1;" : "+l"(a0) : "l"(a2));
            uint32_t lo, hi;
            asm("mov.b64 {%0, %1}, %2;" : "=r"(lo), "=r"(hi) : "l"(a0));
            float part = __uint_as_float(lo) + __uint_as_float(hi);

            // Join helper partial (arrivals posted during the hop -> fast pass)
            asm volatile("bar.sync 1, 256;" ::: "memory");
            float v = xin + part + red[jl];
            float hval;
            asm("tanh.approx.f32 %0, %1;" : "=f"(hval) : "f"(v));

            // Remote publish + arrive FIRST: starts the hop immediately.
            asm volatile("st.shared::cluster.f32 [%0], %1;"
                         :: "r"(p ? r_h0 : r_h1), "f"(hval) : "memory");
            asm volatile("mbarrier.arrive.release.cluster.shared::cluster.b64 _, [%0];"
                         :: "r"(r_mb) : "memory");

            // Local publish + out store, off the remote critical path.
            hb[p ^ 1][j] = hval;
            if (TRANS) out[((size_t)b * HH + j) * TT + t] = hval;
            else       out[((size_t)b * TT + t) * HH + j] = hval;
            asm volatile("bar.arrive 2, 256;" ::: "memory");

            xin = xnext;
            p ^= 1;
        }
    } else {
        for (int t = 0; t < TT; ++t) {
            // Gate on local h of step t-1 (published by waiters, bar 2).
            if (t) asm volatile("bar.sync 2, 256;" ::: "memory");

            const ulonglong2* h4 = (const ulonglong2*)(hb[p] + (kh << 7));
            uint64_t a0 = 0ull, a1 = 0ull, a2 = 0ull, a3 = 0ull;
#pragma unroll
            for (int i = 0; i < 32; i += 2) {
                ulonglong2 hv0 = h4[i];
                ulonglong2 hv1 = h4[i + 1];
                asm("fma.rn.f32x2 %0, %1, %2, %0;" : "+l"(a0) : "l"(w[2*i + 0]), "l"(hv0.x));
                asm("fma.rn.f32x2 %0, %1, %2, %0;" : "+l"(a1) : "l"(w[2*i + 1]), "l"(hv0.y));
                asm("fma.rn.f32x2 %0, %1, %2, %0;" : "+l"(a2) : "l"(w[2*i + 2]), "l"(hv1.x));
                asm("fma.rn.f32x2 %0, %1, %2, %0;" : "+l"(a3) : "l"(w[2*i + 3]), "l"(hv1.y));
            }
            asm("add.rn.f32x2 %0, %0, %1;" : "+l"(a0) : "l"(a1));
            asm("add.rn.f32x2 %0, %0, %1;" : "+l"(a2) : "l"(a3));
            asm("add.rn.f32x2 %0, %0, %1;" : "+l"(a0) : "l"(a2));
            uint32_t lo, hi;
            asm("mov.b64 {%0, %1}, %2;" : "=r"(lo), "=r"(hi) : "l"(a0));
            red[jl] = __uint_as_float(lo) + __uint_as_float(hi);

            // Hand partial to the waiters (non-blocking).
            asm volatile("bar.arrive 1, 256;" ::: "memory");
            p ^= 1;
        }
    }

    asm volatile("barrier.cluster.arrive.aligned;" ::: "memory");
    asm volatile("barrier.cluster.wait.aligned;"   ::: "memory");
}

// ---------------------------------------------------------------------------
// Launch
// ---------------------------------------------------------------------------
extern "C" void kernel_launch(void* const* d_in, const int* in_sizes, int n_in,
                              void* d_out, int out_size)
{
    const float* x     = (const float*)d_in[0];
    const float* W_ih0 = (const float*)d_in[1];
    const float* W_hh0 = (const float*)d_in[2];
    const float* b_ih0 = (const float*)d_in[3];
    const float* b_hh0 = (const float*)d_in[4];
    const float* W_ih1 = (const float*)d_in[5];
    const float* W_hh1 = (const float*)d_in[6];
    const float* b_ih1 = (const float*)d_in[7];
    const float* b_hh1 = (const float*)d_in[8];
    float* out = (float*)d_out;

    float *bufA, *bufB;
    cudaGetSymbolAddress((void**)&bufA, g_bufA);
    cudaGetSymbolAddress((void**)&bufB, g_bufB);

    const int M = BB * TT;  // 65536

    // Layer 1 input projection: bufA = x @ W_ih0^T + (b_ih0 + b_hh0)
    gemm_bias_kernel<<<dim3(HH / 128, M / 128), 256>>>(
        x, W_ih0, b_ih0, b_hh0, bufA, M, HH, DD);

    // Layer 1 recurrence -> bufB = h1 [B,T,H]   (64 clusters of 2 CTAs)
    rec_cluster_kernel<false><<<BB * 2, 256>>>(bufA, W_hh0, bufB);

    // Layer 2 input projection: bufA = h1 @ W_ih1^T + (b_ih1 + b_hh1)
    gemm_bias_kernel<<<dim3(HH / 128, M / 128), 256>>>(
        bufB, W_ih1, b_ih1, b_hh1, bufA, M, HH, HH);

    // Layer 2 recurrence -> out [B,H,T]
    rec_cluster_kernel<true><<<BB * 2, 256>>>(bufA, W_hh1, out);
}